// round 15
// baseline (speedup 1.0000x reference)
#include <cuda_runtime.h>
#include <cuda_bf16.h>
#include <math.h>
#include <stdint.h>

// Problem constants
#define B   64
#define T   2048
#define D   256
#define V   256

#define GRID_CTAS 148               // one wave, 1 CTA/SM (RF-bound at 512 thr)
#define GEMM_CTAS (GRID_CTAS - B)   // 84
// Producer: 512 threads, 2 threads per dim (k-split 128/128).
// Per thread: 80 k-cols in registers (40 x f32x2), 48 k-cols from SMEM.
#define PRWC 80                     // reg cols per thread (per k-half)
#define PSWC 48                     // smem cols per thread (per k-half)
#define SSTR 100                    // Wsm row stride in floats (96 used + 4 pad); 400B=25*16, mod32=4 -> conflict-free
#define CHUNK 128                   // gemm consumes T in chunks of 128 rows

typedef unsigned long long ull;

// Scratch in device globals (no allocations allowed)
__device__ float g_EWx[V * D];              // E @ Wx^T
__device__ float g_EG [V * D];              // sigmoid(E @ Wz^T)
__device__ float g_out[(size_t)B * T * D];  // h_t * gate_t (134 MB)
__device__ int   g_prog[B];                 // per-batch progress (t+1), reset each run

// ---------------------------------------------------------------------------
// f32x2 packed helpers (sm_103a)
// ---------------------------------------------------------------------------
__device__ __forceinline__ ull f2fma(ull a, ull b, ull c) {
    ull d;
    asm("fma.rn.f32x2 %0, %1, %2, %3;" : "=l"(d) : "l"(a), "l"(b), "l"(c));
    return d;
}
__device__ __forceinline__ ull f2add(ull a, ull b) {
    ull d;
    asm("add.rn.f32x2 %0, %1, %2;" : "=l"(d) : "l"(a), "l"(b));
    return d;
}
__device__ __forceinline__ ull f2dup(float x) {
    ull d;
    asm("mov.b64 %0, {%1, %1};" : "=l"(d) : "f"(x));
    return d;
}
__device__ __forceinline__ float f2sum(ull a) {
    float lo, hi;
    asm("mov.b64 {%0, %1}, %2;" : "=f"(lo), "=f"(hi) : "l"(a));
    return lo + hi;
}

// ---------------------------------------------------------------------------
// Kernel 1: precompute token tables as a coalesced dual GEMM (64x64 tiles).
// Also resets g_prog (runs before the fused kernel on the same stream).
// ---------------------------------------------------------------------------
__global__ __launch_bounds__(256)
void precompute_tables(const float* __restrict__ E,
                       const float* __restrict__ Wx,
                       const float* __restrict__ Wz) {
    __shared__ float As[8][64], Bxs[8][64], Bzs[8][64];
    const int m0 = blockIdx.x << 6;
    const int n0 = blockIdx.y << 6;
    const int tid = threadIdx.x;

    if (blockIdx.x == 0 && blockIdx.y == 0 && tid < B) g_prog[tid] = 0;

    const int lr = tid >> 2;
    const int lc = (tid & 3) << 1;
    const int tm = (tid >> 4) << 2;
    const int tn = (tid & 15) << 2;

    float accx[4][4] = {}, accz[4][4] = {};

    for (int k0 = 0; k0 < D; k0 += 8) {
        float2 a2 = *(const float2*)(E  + ((m0 + lr) << 8) + k0 + lc);
        float2 x2 = *(const float2*)(Wx + ((n0 + lr) << 8) + k0 + lc);
        float2 z2 = *(const float2*)(Wz + ((n0 + lr) << 8) + k0 + lc);
        As [lc][lr] = a2.x; As [lc + 1][lr] = a2.y;
        Bxs[lc][lr] = x2.x; Bxs[lc + 1][lr] = x2.y;
        Bzs[lc][lr] = z2.x; Bzs[lc + 1][lr] = z2.y;
        __syncthreads();
#pragma unroll
        for (int kk = 0; kk < 8; kk++) {
            float ar[4], bx[4], bz[4];
#pragma unroll
            for (int i = 0; i < 4; i++) ar[i] = As[kk][tm + i];
#pragma unroll
            for (int j = 0; j < 4; j++) { bx[j] = Bxs[kk][tn + j]; bz[j] = Bzs[kk][tn + j]; }
#pragma unroll
            for (int i = 0; i < 4; i++)
#pragma unroll
                for (int j = 0; j < 4; j++) {
                    accx[i][j] += ar[i] * bx[j];
                    accz[i][j] += ar[i] * bz[j];
                }
        }
        __syncthreads();
    }

#pragma unroll
    for (int i = 0; i < 4; i++)
#pragma unroll
        for (int j = 0; j < 4; j++) {
            int idx = ((m0 + tm + i) << 8) + n0 + tn + j;
            g_EWx[idx] = accx[i][j];
            g_EG [idx] = 1.0f / (1.0f + __expf(-accz[i][j]));
        }
}

// ---------------------------------------------------------------------------
// Kernel 2 (fused, 512 threads):
//  CTAs [0,64): recurrence. Thread (d = tid&255, half = tid>>8) computes the
//  k-range [half*128, half*128+128) of dim d's dot product; per-dim partials
//  combined through SMEM. Warps 0-7 are half 0, warps 8-15 half 1, so all h
//  loads are warp-uniform broadcasts. 16 warps hide LDS/crossbar latency.
//  CTAs [64,148): logits GEMM consumer (128x128 tiles, 8x4 per thread).
//  One wave, 1 CTA/SM (register-file bound) -> producers resident -> no deadlock.
// ---------------------------------------------------------------------------
// SMEM floats: Wsm 256*100 = 25600 | hb 2*256 = 512 | part 512 | toks 2049
#define FUSED_SMEM_BYTES 114944

__global__ __launch_bounds__(512, 1)
void fused_rnn_gemm(const int*   __restrict__ tokens,
                    const float* __restrict__ Wh,
                    const float* __restrict__ E,
                    float*       __restrict__ C) {
    extern __shared__ __align__(16) float smx[];
    const int cid = blockIdx.x;
    const int tid = threadIdx.x;

    if (cid < B) {
        // ================= recurrence producer =================
        float* Wsm  = smx;                       // 256 * SSTR (96 cols used)
        float* hb   = smx + 25600;               // 2 * 256 (double buffer)
        float* part = smx + 26112;               // 512 partials
        int*   toks = (int*)(smx + 26624);       // T + 1

        const int b    = cid;
        const int d    = tid & 255;
        const int half = tid >> 8;

        const int* trow = tokens + b * T;
        for (int i = tid; i < T; i += 512) toks[i] = trow[i];
        if (tid == 0) toks[T] = 0;

        // SMEM weights: dim r, 96 cols: [0,48) <- Wh cols [80,128),
        // [48,96) <- Wh cols [208,256)
        for (int idx = tid; idx < 256 * 96; idx += 512) {
            int r = idx / 96;
            int c = idx - r * 96;
            int src = (c < 48) ? (c + 80) : (c + 160);
            Wsm[r * SSTR + c] = Wh[(r << 8) + src];
        }

        // 80 weight floats in registers as 40 packed f32x2:
        // cols [half*128, half*128+80) of row d
        ull w[40];
        {
            const ull* wp = (const ull*)(Wh + (d << 8) + (half << 7));
#pragma unroll
            for (int q = 0; q < 40; q++) w[q] = wp[q];
        }

        hb[tid & 511] = 0.0f;   // covers both buffers (512 floats)
        __syncthreads();

        float wx = 0.0f, g = 0.0f;
        if (!half) {
            int tk0 = toks[0];
            wx = g_EWx[(tk0 << 8) + d];
            g  = g_EG [(tk0 << 8) + d];
        }

        float* outp = g_out + (size_t)b * T * D + d;
        const ulonglong2* wsp = (const ulonglong2*)(Wsm + d * SSTR + half * PSWC);

        for (int t = 0; t < T; t++) {
            const int buf = t & 1;

            // prefetch next step's table rows (group 0 only)
            float wxn = 0.0f, gn = 0.0f;
            if (!half) {
                int tkn = toks[t + 1];
                wxn = g_EWx[(tkn << 8) + d];
                gn  = g_EG [(tkn << 8) + d];
            }

            // this thread's k-slice of h: 128 floats
            const ulonglong2* hp =
                (const ulonglong2*)(hb + (buf << 8) + (half << 7));
            ull a0 = 0, a1 = 0, a2 = 0, a3 = 0;

            // register-weight part: k-cols [0,80) of slice = 20 ull2 h loads
#pragma unroll
            for (int q = 0; q < 10; q++) {
                ulonglong2 h0 = hp[2 * q + 0];
                ulonglong2 h1 = hp[2 * q + 1];
                a0 = f2fma(w[4 * q + 0], h0.x, a0);
                a1 = f2fma(w[4 * q + 1], h0.y, a1);
                a2 = f2fma(w[4 * q + 2], h1.x, a2);
                a3 = f2fma(w[4 * q + 3], h1.y, a3);
            }
            // smem-weight part: k-cols [80,128) = 12 h + 12 w ull2 loads
#pragma unroll
            for (int q = 0; q < 6; q++) {
                ulonglong2 h0 = hp[20 + 2 * q + 0];
                ulonglong2 h1 = hp[20 + 2 * q + 1];
                ulonglong2 w0 = wsp[2 * q + 0];
                ulonglong2 w1 = wsp[2 * q + 1];
                a0 = f2fma(w0.x, h0.x, a0);
                a1 = f2fma(w0.y, h0.y, a1);
                a2 = f2fma(w1.x, h1.x, a2);
                a3 = f2fma(w1.y, h1.y, a3);
            }

            a0 = f2add(a0, a1);
            a2 = f2add(a2, a3);
            a0 = f2add(a0, a2);
            part[tid] = f2sum(a0);
            __syncthreads();

            if (!half) {
                float s  = part[d] + part[256 + d] + wx;
                float e  = __expf(2.0f * s);
                float hn = 1.0f - __fdividef(2.0f, e + 1.0f);
                hb[((buf ^ 1) << 8) + d] = hn;       // STS first (critical path)
                outp[(size_t)t * D] = hn * g;
                wx = wxn;
                g  = gn;
            }
            __syncthreads();

            // publish progress every 32 steps (release)
            if (((t & 31) == 31) && tid == 0) {
                __threadfence();
                *(volatile int*)&g_prog[b] = t + 1;
            }
        }
    } else {
        // ================= logits GEMM consumer (512 threads) =================
        float* As = smx;           // [8][128]
        float* Bs = smx + 1024;    // [8][128]

        const int lr = tid >> 2;          // 0..127 load row
        const int lc = (tid & 3) << 1;    // 0,2,4,6 load col pair
        const int tm = (tid >> 5) << 3;   // 8-row group
        const int tv = (tid & 31) << 2;   // 4-col group

        const int njobs = B * (T / CHUNK) * (V / 128);   // 2048

        for (int j = cid - B; j < njobs; j += GEMM_CTAS) {
            const int tc  = j >> 7;          // chunk index (t-major)
            const int rem = j & 127;
            const int bb  = rem >> 1;
            const int vt  = rem & 1;

            if (tid == 0) {
                const int need = (tc + 1) * CHUNK;
                unsigned ns = 64;
                while (*(volatile int*)&g_prog[bb] < need) {
                    __nanosleep(ns);
                    if (ns < 1024) ns <<= 1;
                }
                __threadfence();
            }
            __syncthreads();

            const size_t m0 = (size_t)bb * T + (size_t)tc * CHUNK;
            const int v0 = vt << 7;

            ull acc[8][2];
#pragma unroll
            for (int i = 0; i < 8; i++) { acc[i][0] = 0ull; acc[i][1] = 0ull; }

            const float* Ag = g_out + (m0 + lr) * D + lc;
            const float* Bg = E + ((v0 + lr) << 8) + lc;

            float2 a2v = *(const float2*)(Ag);
            float2 b2v = *(const float2*)(Bg);

            for (int k0 = 0; k0 < D; k0 += 8) {
                As[(lc + 0) * 128 + lr] = a2v.x; As[(lc + 1) * 128 + lr] = a2v.y;
                Bs[(lc + 0) * 128 + lr] = b2v.x; Bs[(lc + 1) * 128 + lr] = b2v.y;
                __syncthreads();
                if (k0 + 8 < D) {
                    a2v = *(const float2*)(Ag + k0 + 8);
                    b2v = *(const float2*)(Bg + k0 + 8);
                }
#pragma unroll
                for (int kk = 0; kk < 8; kk++) {
                    float ar[8];
#pragma unroll
                    for (int i = 0; i < 8; i++) ar[i] = As[kk * 128 + tm + i];
                    const ull* bp = (const ull*)&Bs[kk * 128 + tv];
                    ull br0 = bp[0], br1 = bp[1];
#pragma unroll
                    for (int i = 0; i < 8; i++) {
                        ull ad = f2dup(ar[i]);
                        acc[i][0] = f2fma(ad, br0, acc[i][0]);
                        acc[i][1] = f2fma(ad, br1, acc[i][1]);
                    }
                }
                __syncthreads();
            }

#pragma unroll
            for (int i = 0; i < 8; i++) {
                float* Cp = C + (m0 + tm + i) * V + v0 + tv;
                *(ulonglong2*)Cp = make_ulonglong2(acc[i][0], acc[i][1]);
            }
        }
    }
}

// ---------------------------------------------------------------------------
extern "C" void kernel_launch(void* const* d_in, const int* in_sizes, int n_in,
                              void* d_out, int out_size) {
    const int*   tokens = (const int*)  d_in[0];
    const float* E      = (const float*)d_in[1];
    const float* Wx     = (const float*)d_in[2];
    const float* Wh     = (const float*)d_in[3];
    const float* Wz     = (const float*)d_in[4];
    float* logits = (float*)d_out;

    dim3 pgrid(4, 4);
    precompute_tables<<<pgrid, 256>>>(E, Wx, Wz);

    cudaFuncSetAttribute(fused_rnn_gemm,
                         cudaFuncAttributeMaxDynamicSharedMemorySize,
                         FUSED_SMEM_BYTES);
    fused_rnn_gemm<<<GRID_CTAS, 512, FUSED_SMEM_BYTES>>>(tokens, Wh, E, logits);
}